// round 1
// baseline (speedup 1.0000x reference)
#include <cuda_runtime.h>
#include <math.h>

#define Bv 8
#define Sv 4096
#define Dv 768
#define NIMG 1024
#define FFv 3072
#define CAPv 640
#define Hv 12
#define DHv 64
#define SOCv 3
#define EOSv 2

// ---------------- scratch (device globals; no allocation allowed) -------------
__device__ float g_x  [Bv*CAPv*Dv];
__device__ float g_ln [Bv*CAPv*Dv];
__device__ float g_q  [Bv*CAPv*Dv];
__device__ float g_k  [Bv*NIMG*Dv];
__device__ float g_v  [Bv*NIMG*Dv];
__device__ float g_ao [Bv*CAPv*Dv];
__device__ float g_tmp[Bv*CAPv*Dv];
__device__ float g_ff [Bv*CAPv*FFv];
__device__ float g_sc [(size_t)Bv*Hv*CAPv*NIMG];
__device__ int   g_pos[Bv*Sv];
__device__ int   g_soc[Bv*Sv];
__device__ int   g_cnt[Bv];

// ---------------- SOC/EOS prefix scan: 1 block per batch row ------------------
__global__ void scan_kernel(const int* __restrict__ seq) {
    __shared__ int sh[512];
    __shared__ int pref[513];
    int b = blockIdx.x, t = threadIdx.x;
    const int* row = seq + b * Sv;
    int tok[8];
#pragma unroll
    for (int i = 0; i < 8; i++) tok[i] = row[t * 8 + i];

    int e = 0;
#pragma unroll
    for (int i = 0; i < 8; i++) e += (tok[i] == EOSv);
    sh[t] = e;
    __syncthreads();
    if (t == 0) { int a = 0; for (int i = 0; i < 512; i++) { pref[i] = a; a += sh[i]; } pref[512] = a; }
    __syncthreads();
    int ebefore = pref[t];

    int ecur = ebefore, sc = 0;
#pragma unroll
    for (int i = 0; i < 8; i++) { if (tok[i] == SOCv && ecur == 0) sc++; ecur += (tok[i] == EOSv); }
    __syncthreads();
    sh[t] = sc;
    __syncthreads();
    if (t == 0) { int a = 0; for (int i = 0; i < 512; i++) { pref[i] = a; a += sh[i]; } pref[512] = a; }
    __syncthreads();

    int p = pref[t];
    ecur = ebefore;
#pragma unroll
    for (int i = 0; i < 8; i++) {
        int idx = b * Sv + t * 8 + i;
        bool v = (tok[i] == SOCv && ecur == 0);
        g_soc[idx] = v ? 1 : 0;
        g_pos[idx] = v ? p : CAPv;
        if (v) p++;
        ecur += (tok[i] == EOSv);
    }
    if (t == 0) g_cnt[b] = pref[512];
}

// ---------------- extract: pack SOC rows of hid into g_x ----------------------
__global__ void zero_buf(float* __restrict__ x, long long n) {
    long long i = (long long)blockIdx.x * blockDim.x + threadIdx.x;
    if (i < n) x[i] = 0.f;
}

__global__ void extract_kernel(const float* __restrict__ hid) {
    int t = blockIdx.x;          // token index over B*S
    if (!g_soc[t]) return;
    int p = g_pos[t];
    if (p >= CAPv) return;       // overflow slots dropped (matches jax OOB scatter)
    int b = t / Sv;
    const float* src = hid + (long long)t * Dv;
    float* dst = g_x + ((long long)(b * CAPv + p)) * Dv;
    for (int d = threadIdx.x; d < Dv; d += blockDim.x) dst[d] = src[d];
}

// ---------------- LayerNorm (1 block per row of 768) --------------------------
__global__ void ln_rows(const float* __restrict__ x, float* __restrict__ y,
                        const float* __restrict__ g, const float* __restrict__ be) {
    int row = blockIdx.x;
    const float* px = x + (long long)row * Dv;
    float* py = y + (long long)row * Dv;
    __shared__ float red[64];
    float s = 0.f, s2 = 0.f;
    for (int d = threadIdx.x; d < Dv; d += blockDim.x) { float v = px[d]; s += v; s2 += v * v; }
#pragma unroll
    for (int o = 16; o > 0; o >>= 1) { s += __shfl_down_sync(~0u, s, o); s2 += __shfl_down_sync(~0u, s2, o); }
    int lane = threadIdx.x & 31, w = threadIdx.x >> 5;
    if (lane == 0) { red[w] = s; red[w + 32] = s2; }
    __syncthreads();
    if (threadIdx.x == 0) {
        float a = 0.f, a2 = 0.f;
        for (int i = 0; i < (int)(blockDim.x >> 5); i++) { a += red[i]; a2 += red[i + 32]; }
        float mu = a / Dv;
        float var = a2 / Dv - mu * mu;
        red[0] = mu;
        red[1] = rsqrtf(var + 1e-5f);
    }
    __syncthreads();
    float mu = red[0], rs = red[1];
    for (int d = threadIdx.x; d < Dv; d += blockDim.x)
        py[d] = (px[d] - mu) * rs * g[d] + be[d];
}

// ---------------- batched tiled SGEMM -----------------------------------------
// C[M,N] = alpha * A[M,K] @ op(B);  TRANSB=0: B[K,N], TRANSB=1: B[N,K]^T
// batch decomposed as z = b*Hn + h with separate b/h pointer strides.
template <int TRANSB>
__global__ void __launch_bounds__(256)
sgemm(const float* __restrict__ A, const float* __restrict__ Bm, float* __restrict__ C,
      int M, int Nn, int K, int lda, int ldb, int ldc,
      int Hn, long long sAb, long long sAh, long long sBb, long long sBh,
      long long sCb, long long sCh, float alpha) {
    int z = blockIdx.z;
    int bb = z / Hn, hh = z % Hn;
    A += bb * sAb + hh * sAh;
    Bm += bb * sBb + hh * sBh;
    C += bb * sCb + hh * sCh;

    __shared__ float As[64][17];
    __shared__ float Bs[16][65];
    int tx = threadIdx.x, ty = threadIdx.y, tid = ty * 16 + tx;
    int rb = blockIdx.y * 64, cb = blockIdx.x * 64;
    float acc[4][4] = {};

    for (int k0 = 0; k0 < K; k0 += 16) {
#pragma unroll
        for (int i = 0; i < 4; i++) {
            int idx = tid + i * 256;
            int r = idx >> 4, c = idx & 15;
            int gr = rb + r, gc = k0 + c;
            As[r][c] = (gr < M && gc < K) ? A[(long long)gr * lda + gc] : 0.f;
        }
#pragma unroll
        for (int i = 0; i < 4; i++) {
            int idx = tid + i * 256;
            if (TRANSB) {
                int cc = idx >> 4, r = idx & 15;       // k fastest -> coalesced along K
                int gn = cb + cc, gk = k0 + r;
                Bs[r][cc] = (gn < Nn && gk < K) ? Bm[(long long)gn * ldb + gk] : 0.f;
            } else {
                int r = idx >> 6, cc = idx & 63;       // n fastest -> coalesced along N
                int gk = k0 + r, gn = cb + cc;
                Bs[r][cc] = (gk < K && gn < Nn) ? Bm[(long long)gk * ldb + gn] : 0.f;
            }
        }
        __syncthreads();
#pragma unroll
        for (int k = 0; k < 16; k++) {
            float a[4], bq[4];
#pragma unroll
            for (int r = 0; r < 4; r++) a[r] = As[ty * 4 + r][k];
#pragma unroll
            for (int c = 0; c < 4; c++) bq[c] = Bs[k][tx * 4 + c];
#pragma unroll
            for (int r = 0; r < 4; r++)
#pragma unroll
                for (int c = 0; c < 4; c++) acc[r][c] += a[r] * bq[c];
        }
        __syncthreads();
    }
#pragma unroll
    for (int r = 0; r < 4; r++) {
        int gr = rb + ty * 4 + r;
        if (gr >= M) continue;
#pragma unroll
        for (int c = 0; c < 4; c++) {
            int gc = cb + tx * 4 + c;
            if (gc < Nn) C[(long long)gr * ldc + gc] = alpha * acc[r][c];
        }
    }
}

// ---------------- masked softmax over score rows ------------------------------
__global__ void softmax_rows(float* __restrict__ sc, int Lk, int useMask) {
    long long row = blockIdx.x;                 // over B*H*CAP
    int b = (int)(row / (Hv * CAPv));
    float* p = sc + row * (long long)Lk;
    int c = useMask ? g_cnt[b] : Lk;
    __shared__ float red[32];
    int lane = threadIdx.x & 31, w = threadIdx.x >> 5;
    int nw = blockDim.x >> 5;

    float m = -3e38f;
    for (int i = threadIdx.x; i < Lk; i += blockDim.x) {
        float v = (i < c) ? p[i] : -1e9f;
        m = fmaxf(m, v);
    }
#pragma unroll
    for (int o = 16; o > 0; o >>= 1) m = fmaxf(m, __shfl_down_sync(~0u, m, o));
    if (lane == 0) red[w] = m;
    __syncthreads();
    if (threadIdx.x == 0) { float a = -3e38f; for (int i = 0; i < nw; i++) a = fmaxf(a, red[i]); red[0] = a; }
    __syncthreads();
    m = red[0];
    __syncthreads();

    float s = 0.f;
    for (int i = threadIdx.x; i < Lk; i += blockDim.x) {
        float v = (i < c) ? p[i] : -1e9f;
        float e = expf(v - m);     // exp(-1e9 - m) underflows to exactly 0, matching ref
        p[i] = e;
        s += e;
    }
#pragma unroll
    for (int o = 16; o > 0; o >>= 1) s += __shfl_down_sync(~0u, s, o);
    if (lane == 0) red[w] = s;
    __syncthreads();
    if (threadIdx.x == 0) { float a = 0.f; for (int i = 0; i < nw; i++) a += red[i]; red[0] = a; }
    __syncthreads();
    float inv = 1.f / red[0];
    for (int i = threadIdx.x; i < Lk; i += blockDim.x) p[i] *= inv;
}

// ---------------- elementwise ---------------------------------------------------
__global__ void add_inplace(float* __restrict__ x, const float* __restrict__ t, long long n) {
    long long i = (long long)blockIdx.x * blockDim.x + threadIdx.x;
    if (i < n) x[i] += t[i];
}

__global__ void gelu_inplace(float* __restrict__ x, long long n) {
    long long i = (long long)blockIdx.x * blockDim.x + threadIdx.x;
    if (i < n) {
        float v = x[i];
        float u = 0.7978845608028654f * (v + 0.044715f * v * v * v);
        x[i] = 0.5f * v * (1.f + tanhf(u));
    }
}

// ---------------- outputs -------------------------------------------------------
__global__ void write_hid(const float* __restrict__ hid, float* __restrict__ out) {
    long long idx = (long long)blockIdx.x * blockDim.x + threadIdx.x;
    if (idx >= (long long)Bv * Sv * Dv) return;
    int d = (int)(idx % Dv);
    long long tok = idx / Dv;        // b*S + s
    int b = (int)(tok / Sv);
    if (g_soc[tok]) {
        int p = g_pos[tok];
        if (p > CAPv - 1) p = CAPv - 1;
        out[idx] = g_x[((long long)(b * CAPv + p)) * Dv + d];
    } else {
        out[idx] = hid[idx];
    }
}

__global__ void write_x(float* __restrict__ out) {
    long long idx = (long long)blockIdx.x * blockDim.x + threadIdx.x;
    if (idx < (long long)Bv * CAPv * Dv)
        out[(long long)Bv * Sv * Dv + idx] = g_x[idx];
}

// ---------------- launch --------------------------------------------------------
extern "C" void kernel_launch(void* const* d_in, const int* in_sizes, int n_in,
                              void* d_out, int out_size) {
    const float* img   = (const float*)d_in[0];
    const float* hid   = (const float*)d_in[1];
    const int*   seq   = (const int*)  d_in[2];
    const float* wq_s  = (const float*)d_in[3];
    const float* wk_s  = (const float*)d_in[4];
    const float* wv_s  = (const float*)d_in[5];
    const float* wo_s  = (const float*)d_in[6];
    const float* wq_c  = (const float*)d_in[7];
    const float* wk_c  = (const float*)d_in[8];
    const float* wv_c  = (const float*)d_in[9];
    const float* wo_c  = (const float*)d_in[10];
    const float* w_ff1 = (const float*)d_in[11];
    const float* w_ff2 = (const float*)d_in[12];
    const float* ln1_s = (const float*)d_in[13];
    const float* ln1_b = (const float*)d_in[14];
    const float* ln2_s = (const float*)d_in[15];
    const float* ln2_b = (const float*)d_in[16];
    const float* ln3_s = (const float*)d_in[17];
    const float* ln3_b = (const float*)d_in[18];
    float* out = (float*)d_out;

    float *x, *lnb, *q, *k, *v, *ao, *tmp, *ff, *sc;
    cudaGetSymbolAddress((void**)&x,   g_x);
    cudaGetSymbolAddress((void**)&lnb, g_ln);
    cudaGetSymbolAddress((void**)&q,   g_q);
    cudaGetSymbolAddress((void**)&k,   g_k);
    cudaGetSymbolAddress((void**)&v,   g_v);
    cudaGetSymbolAddress((void**)&ao,  g_ao);
    cudaGetSymbolAddress((void**)&tmp, g_tmp);
    cudaGetSymbolAddress((void**)&ff,  g_ff);
    cudaGetSymbolAddress((void**)&sc,  g_sc);

    const long long nX = (long long)Bv * CAPv * Dv;   // 3,932,160
    dim3 thr(16, 16);

    // index machinery + extraction
    scan_kernel<<<Bv, 512>>>(seq);
    zero_buf<<<(int)((nX + 255) / 256), 256>>>(x, nX);
    extract_kernel<<<Bv * Sv, 192>>>(hid);

    // ---- block 1: masked self-attention -------------------------------------
    ln_rows<<<Bv * CAPv, 256>>>(x, lnb, ln1_s, ln1_b);
    sgemm<0><<<dim3(12, 80, 1), thr>>>(lnb, wq_s, q, 5120, 768, 768, 768, 768, 768, 1, 0,0,0,0,0,0, 1.f);
    sgemm<0><<<dim3(12, 80, 1), thr>>>(lnb, wk_s, k, 5120, 768, 768, 768, 768, 768, 1, 0,0,0,0,0,0, 1.f);
    sgemm<0><<<dim3(12, 80, 1), thr>>>(lnb, wv_s, v, 5120, 768, 768, 768, 768, 768, 1, 0,0,0,0,0,0, 1.f);
    // scores[b,h] = Q K^T / 8 ; z = b*H + h
    sgemm<1><<<dim3(10, 10, Bv * Hv), thr>>>(q, k, sc, CAPv, CAPv, DHv, Dv, Dv, CAPv,
        Hv, (long long)CAPv * Dv, DHv, (long long)CAPv * Dv, DHv,
        (long long)Hv * CAPv * CAPv, (long long)CAPv * CAPv, 0.125f);
    softmax_rows<<<Bv * Hv * CAPv, 256>>>(sc, CAPv, 1);
    sgemm<0><<<dim3(1, 10, Bv * Hv), thr>>>(sc, v, ao, CAPv, DHv, CAPv, CAPv, Dv, Dv,
        Hv, (long long)Hv * CAPv * CAPv, (long long)CAPv * CAPv,
        (long long)CAPv * Dv, DHv, (long long)CAPv * Dv, DHv, 1.f);
    sgemm<0><<<dim3(12, 80, 1), thr>>>(ao, wo_s, tmp, 5120, 768, 768, 768, 768, 768, 1, 0,0,0,0,0,0, 1.f);
    add_inplace<<<(int)((nX + 255) / 256), 256>>>(x, tmp, nX);

    // ---- block 2: cross-attention to img ------------------------------------
    ln_rows<<<Bv * CAPv, 256>>>(x, lnb, ln2_s, ln2_b);
    sgemm<0><<<dim3(12, 80, 1),  thr>>>(lnb, wq_c, q, 5120, 768, 768, 768, 768, 768, 1, 0,0,0,0,0,0, 1.f);
    sgemm<0><<<dim3(12, 128, 1), thr>>>(img, wk_c, k, 8192, 768, 768, 768, 768, 768, 1, 0,0,0,0,0,0, 1.f);
    sgemm<0><<<dim3(12, 128, 1), thr>>>(img, wv_c, v, 8192, 768, 768, 768, 768, 768, 1, 0,0,0,0,0,0, 1.f);
    sgemm<1><<<dim3(16, 10, Bv * Hv), thr>>>(q, k, sc, CAPv, NIMG, DHv, Dv, Dv, NIMG,
        Hv, (long long)CAPv * Dv, DHv, (long long)NIMG * Dv, DHv,
        (long long)Hv * CAPv * NIMG, (long long)CAPv * NIMG, 0.125f);
    softmax_rows<<<Bv * Hv * CAPv, 256>>>(sc, NIMG, 0);
    sgemm<0><<<dim3(1, 10, Bv * Hv), thr>>>(sc, v, ao, CAPv, DHv, NIMG, NIMG, Dv, Dv,
        Hv, (long long)Hv * CAPv * NIMG, (long long)CAPv * NIMG,
        (long long)NIMG * Dv, DHv, (long long)CAPv * Dv, DHv, 1.f);
    sgemm<0><<<dim3(12, 80, 1), thr>>>(ao, wo_c, tmp, 5120, 768, 768, 768, 768, 768, 1, 0,0,0,0,0,0, 1.f);
    add_inplace<<<(int)((nX + 255) / 256), 256>>>(x, tmp, nX);

    // ---- FFN ------------------------------------------------------------------
    ln_rows<<<Bv * CAPv, 256>>>(x, lnb, ln3_s, ln3_b);
    sgemm<0><<<dim3(48, 80, 1), thr>>>(lnb, w_ff1, ff, 5120, FFv, 768, 768, FFv, FFv, 1, 0,0,0,0,0,0, 1.f);
    gelu_inplace<<<(int)(((long long)5120 * FFv + 255) / 256), 256>>>(ff, (long long)5120 * FFv);
    sgemm<0><<<dim3(12, 80, 1), thr>>>(ff, w_ff2, tmp, 5120, 768, FFv, FFv, 768, 768, 1, 0,0,0,0,0,0, 1.f);
    add_inplace<<<(int)((nX + 255) / 256), 256>>>(x, tmp, nX);

    // ---- outputs: [hid_new | x] ----------------------------------------------
    write_hid<<<(int)(((long long)Bv * Sv * Dv + 255) / 256), 256>>>(hid, out);
    write_x<<<(int)((nX + 255) / 256), 256>>>(out);
}

// round 6
// speedup vs baseline: 1.4891x; 1.4891x over previous
#include <cuda_runtime.h>
#include <math.h>
#include <stdint.h>

#define Bv 8
#define Sv 4096
#define Dv 768
#define NIMG 1024
#define FFv 3072
#define CAPv 640
#define Hv 12
#define DHv 64
#define SOCv 3
#define EOSv 2

// ---------------- scratch (device globals; no allocation allowed) -------------
__device__ float g_x  [Bv*CAPv*Dv];
__device__ float g_ln [Bv*CAPv*Dv];
__device__ float g_q  [Bv*CAPv*Dv];
__device__ float g_k  [Bv*NIMG*Dv];
__device__ float g_v  [Bv*NIMG*Dv];
__device__ float g_ao [Bv*CAPv*Dv];
__device__ float g_tmp[Bv*CAPv*Dv];
__device__ float g_ff [Bv*CAPv*FFv];
__device__ float g_sc [(size_t)Bv*Hv*CAPv*NIMG];
__device__ int   g_pos[Bv*Sv];
__device__ int   g_soc[Bv*Sv];
__device__ int   g_cnt[Bv];

// ---------------- SOC/EOS prefix scan: 1 block per batch row ------------------
__global__ void scan_kernel(const int* __restrict__ seq) {
    __shared__ int sh[512];
    __shared__ int pref[513];
    int b = blockIdx.x, t = threadIdx.x;
    const int* row = seq + b * Sv;
    int tok[8];
#pragma unroll
    for (int i = 0; i < 8; i++) tok[i] = row[t * 8 + i];

    int e = 0;
#pragma unroll
    for (int i = 0; i < 8; i++) e += (tok[i] == EOSv);
    sh[t] = e;
    __syncthreads();
    if (t == 0) { int a = 0; for (int i = 0; i < 512; i++) { pref[i] = a; a += sh[i]; } pref[512] = a; }
    __syncthreads();
    int ebefore = pref[t];

    int ecur = ebefore, sc = 0;
#pragma unroll
    for (int i = 0; i < 8; i++) { if (tok[i] == SOCv && ecur == 0) sc++; ecur += (tok[i] == EOSv); }
    __syncthreads();
    sh[t] = sc;
    __syncthreads();
    if (t == 0) { int a = 0; for (int i = 0; i < 512; i++) { pref[i] = a; a += sh[i]; } pref[512] = a; }
    __syncthreads();

    int p = pref[t];
    ecur = ebefore;
#pragma unroll
    for (int i = 0; i < 8; i++) {
        int idx = b * Sv + t * 8 + i;
        bool v = (tok[i] == SOCv && ecur == 0);
        g_soc[idx] = v ? 1 : 0;
        g_pos[idx] = v ? p : CAPv;
        if (v) p++;
        ecur += (tok[i] == EOSv);
    }
    if (t == 0) g_cnt[b] = pref[512];
}

// ---------------- extract: pack SOC rows of hid into g_x ----------------------
__global__ void zero_buf(float* __restrict__ x, long long n) {
    long long i = (long long)blockIdx.x * blockDim.x + threadIdx.x;
    if (i < n) x[i] = 0.f;
}

__global__ void extract_kernel(const float* __restrict__ hid) {
    int t = blockIdx.x;          // token index over B*S
    if (!g_soc[t]) return;
    int p = g_pos[t];
    if (p >= CAPv) return;
    int b = t / Sv;
    const float* src = hid + (long long)t * Dv;
    float* dst = g_x + ((long long)(b * CAPv + p)) * Dv;
    for (int d = threadIdx.x; d < Dv; d += blockDim.x) dst[d] = src[d];
}

// ---------------- LayerNorm (1 block per row of 768) --------------------------
__global__ void ln_rows(const float* __restrict__ x, float* __restrict__ y,
                        const float* __restrict__ g, const float* __restrict__ be) {
    int row = blockIdx.x;
    const float* px = x + (long long)row * Dv;
    float* py = y + (long long)row * Dv;
    __shared__ float red[64];
    float s = 0.f, s2 = 0.f;
    for (int d = threadIdx.x; d < Dv; d += blockDim.x) { float v = px[d]; s += v; s2 += v * v; }
#pragma unroll
    for (int o = 16; o > 0; o >>= 1) { s += __shfl_down_sync(~0u, s, o); s2 += __shfl_down_sync(~0u, s2, o); }
    int lane = threadIdx.x & 31, w = threadIdx.x >> 5;
    if (lane == 0) { red[w] = s; red[w + 32] = s2; }
    __syncthreads();
    if (threadIdx.x == 0) {
        float a = 0.f, a2 = 0.f;
        for (int i = 0; i < (int)(blockDim.x >> 5); i++) { a += red[i]; a2 += red[i + 32]; }
        float mu = a / Dv;
        float var = a2 / Dv - mu * mu;
        red[0] = mu;
        red[1] = rsqrtf(var + 1e-5f);
    }
    __syncthreads();
    float mu = red[0], rs = red[1];
    for (int d = threadIdx.x; d < Dv; d += blockDim.x)
        py[d] = (px[d] - mu) * rs * g[d] + be[d];
}

// ---------------- TF32 tensor-core batched GEMM --------------------------------
// C[M,N] = alpha * A[M,K] @ op(B);  TRANSB=0: B[K,N], TRANSB=1: B[N,K]^T
// block tile 128x64x32, 8 warps (4 M x 2 N), warp tile 32x32, mma m16n8k8 tf32.
__device__ __forceinline__ uint32_t f2tf32(float v) {
    uint32_t u;
    asm("cvt.rna.tf32.f32 %0, %1;" : "=r"(u) : "f"(v));
    return u;
}

__device__ __forceinline__ void mma_tf32(float* d, const uint32_t* a, const uint32_t* b) {
    asm volatile(
        "mma.sync.aligned.m16n8k8.row.col.f32.tf32.tf32.f32 "
        "{%0,%1,%2,%3},{%4,%5,%6,%7},{%8,%9},{%0,%1,%2,%3};"
        : "+f"(d[0]), "+f"(d[1]), "+f"(d[2]), "+f"(d[3])
        : "r"(a[0]), "r"(a[1]), "r"(a[2]), "r"(a[3]), "r"(b[0]), "r"(b[1]));
}

template <int TRANSB>
__global__ void __launch_bounds__(256)
mma_gemm(const float* __restrict__ A, const float* __restrict__ Bm, float* __restrict__ C,
         int M, int Nn, int K, int lda, int ldb, int ldc,
         int Hn, long long sAb, long long sAh, long long sBb, long long sBh,
         long long sCb, long long sCh, float alpha) {
    int z = blockIdx.z;
    int bb = z / Hn, hh = z % Hn;
    A += bb * sAb + hh * sAh;
    Bm += bb * sBb + hh * sBh;
    C += bb * sCb + hh * sCh;

    __shared__ float As[128][36];   // [m][k], pad -> conflict-free frag loads
    __shared__ float Bs[32][68];    // [k][n]

    int tid = threadIdx.x;
    int lane = tid & 31, warp = tid >> 5;
    int wm = warp >> 1, wn = warp & 1;        // 4 x 2 warp grid
    int g = lane >> 2, cq = lane & 3;
    int rb = blockIdx.y * 128, cb = blockIdx.x * 64;

    float acc[2][4][4];
#pragma unroll
    for (int mi = 0; mi < 2; mi++)
#pragma unroll
        for (int ni = 0; ni < 4; ni++)
#pragma unroll
            for (int i = 0; i < 4; i++) acc[mi][ni][i] = 0.f;

    for (int k0 = 0; k0 < K; k0 += 32) {
        // stage A (128x32), coalesced along k
#pragma unroll
        for (int i = 0; i < 16; i++) {
            int idx = tid + i * 256;
            int r = idx >> 5, c = idx & 31;
            int gr = rb + r, gc = k0 + c;
            float v = (gr < M && gc < K) ? A[(long long)gr * lda + gc] : 0.f;
            As[r][c] = __uint_as_float(f2tf32(v));
        }
        // stage B (32x64)
#pragma unroll
        for (int i = 0; i < 8; i++) {
            int idx = tid + i * 256;
            if (TRANSB) {
                int n = idx >> 5, kk = idx & 31;           // coalesced along K
                int gn = cb + n, gk = k0 + kk;
                float v = (gn < Nn && gk < K) ? Bm[(long long)gn * ldb + gk] : 0.f;
                Bs[kk][n] = __uint_as_float(f2tf32(v));
            } else {
                int kk = idx >> 6, n = idx & 63;           // coalesced along N
                int gk = k0 + kk, gn = cb + n;
                float v = (gk < K && gn < Nn) ? Bm[(long long)gk * ldb + gn] : 0.f;
                Bs[kk][n] = __uint_as_float(f2tf32(v));
            }
        }
        __syncthreads();

#pragma unroll
        for (int ks = 0; ks < 4; ks++) {
            int kk = ks * 8;
            uint32_t a[2][4], b[4][2];
#pragma unroll
            for (int mi = 0; mi < 2; mi++) {
                int row = wm * 32 + mi * 16 + g;
                a[mi][0] = __float_as_uint(As[row][kk + cq]);
                a[mi][1] = __float_as_uint(As[row + 8][kk + cq]);
                a[mi][2] = __float_as_uint(As[row][kk + cq + 4]);
                a[mi][3] = __float_as_uint(As[row + 8][kk + cq + 4]);
            }
#pragma unroll
            for (int ni = 0; ni < 4; ni++) {
                int col = wn * 32 + ni * 8 + g;
                b[ni][0] = __float_as_uint(Bs[kk + cq][col]);
                b[ni][1] = __float_as_uint(Bs[kk + cq + 4][col]);
            }
#pragma unroll
            for (int mi = 0; mi < 2; mi++)
#pragma unroll
                for (int ni = 0; ni < 4; ni++)
                    mma_tf32(acc[mi][ni], a[mi], b[ni]);
        }
        __syncthreads();
    }

    // epilogue
#pragma unroll
    for (int mi = 0; mi < 2; mi++) {
        int row0 = rb + wm * 32 + mi * 16 + g;
#pragma unroll
        for (int ni = 0; ni < 4; ni++) {
            int col0 = cb + wn * 32 + ni * 8 + 2 * cq;
            if (row0 < M) {
                if (col0 < Nn)     C[(long long)row0 * ldc + col0]     = alpha * acc[mi][ni][0];
                if (col0 + 1 < Nn) C[(long long)row0 * ldc + col0 + 1] = alpha * acc[mi][ni][1];
            }
            if (row0 + 8 < M) {
                if (col0 < Nn)     C[(long long)(row0 + 8) * ldc + col0]     = alpha * acc[mi][ni][2];
                if (col0 + 1 < Nn) C[(long long)(row0 + 8) * ldc + col0 + 1] = alpha * acc[mi][ni][3];
            }
        }
    }
}

// ---------------- masked softmax over score rows ------------------------------
__global__ void softmax_rows(float* __restrict__ sc, int Lk, int useMask) {
    long long row = blockIdx.x;                 // over B*H*CAP
    int b = (int)(row / (Hv * CAPv));
    float* p = sc + row * (long long)Lk;
    int c = useMask ? g_cnt[b] : Lk;
    __shared__ float red[32];
    int lane = threadIdx.x & 31, w = threadIdx.x >> 5;
    int nw = blockDim.x >> 5;

    float m = -3e38f;
    for (int i = threadIdx.x; i < Lk; i += blockDim.x) {
        float v = (i < c) ? p[i] : -1e9f;
        m = fmaxf(m, v);
    }
#pragma unroll
    for (int o = 16; o > 0; o >>= 1) m = fmaxf(m, __shfl_down_sync(~0u, m, o));
    if (lane == 0) red[w] = m;
    __syncthreads();
    if (threadIdx.x == 0) { float a = -3e38f; for (int i = 0; i < nw; i++) a = fmaxf(a, red[i]); red[0] = a; }
    __syncthreads();
    m = red[0];
    __syncthreads();

    float s = 0.f;
    for (int i = threadIdx.x; i < Lk; i += blockDim.x) {
        float v = (i < c) ? p[i] : -1e9f;
        float e = expf(v - m);
        p[i] = e;
        s += e;
    }
#pragma unroll
    for (int o = 16; o > 0; o >>= 1) s += __shfl_down_sync(~0u, s, o);
    if (lane == 0) red[w] = s;
    __syncthreads();
    if (threadIdx.x == 0) { float a = 0.f; for (int i = 0; i < nw; i++) a += red[i]; red[0] = a; }
    __syncthreads();
    float inv = 1.f / red[0];
    for (int i = threadIdx.x; i < Lk; i += blockDim.x) p[i] *= inv;
}

// ---------------- elementwise ---------------------------------------------------
__global__ void add_inplace(float* __restrict__ x, const float* __restrict__ t, long long n) {
    long long i = (long long)blockIdx.x * blockDim.x + threadIdx.x;
    if (i < n) x[i] += t[i];
}

__global__ void gelu_inplace(float* __restrict__ x, long long n) {
    long long i = (long long)blockIdx.x * blockDim.x + threadIdx.x;
    if (i < n) {
        float v = x[i];
        float u = 0.7978845608028654f * (v + 0.044715f * v * v * v);
        x[i] = 0.5f * v * (1.f + tanhf(u));
    }
}

// ---------------- outputs -------------------------------------------------------
__global__ void write_hid(const float* __restrict__ hid, float* __restrict__ out) {
    long long idx = (long long)blockIdx.x * blockDim.x + threadIdx.x;
    if (idx >= (long long)Bv * Sv * Dv) return;
    int d = (int)(idx % Dv);
    long long tok = idx / Dv;
    int b = (int)(tok / Sv);
    if (g_soc[tok]) {
        int p = g_pos[tok];
        if (p > CAPv - 1) p = CAPv - 1;
        out[idx] = g_x[((long long)(b * CAPv + p)) * Dv + d];
    } else {
        out[idx] = hid[idx];
    }
}

__global__ void write_x(float* __restrict__ out) {
    long long idx = (long long)blockIdx.x * blockDim.x + threadIdx.x;
    if (idx < (long long)Bv * CAPv * Dv)
        out[(long long)Bv * Sv * Dv + idx] = g_x[idx];
}

// ---------------- launch --------------------------------------------------------
extern "C" void kernel_launch(void* const* d_in, const int* in_sizes, int n_in,
                              void* d_out, int out_size) {
    const float* img   = (const float*)d_in[0];
    const float* hid   = (const float*)d_in[1];
    const int*   seq   = (const int*)  d_in[2];
    const float* wq_s  = (const float*)d_in[3];
    const float* wk_s  = (const float*)d_in[4];
    const float* wv_s  = (const float*)d_in[5];
    const float* wo_s  = (const float*)d_in[6];
    const float* wq_c  = (const float*)d_in[7];
    const float* wk_c  = (const float*)d_in[8];
    const float* wv_c  = (const float*)d_in[9];
    const float* wo_c  = (const float*)d_in[10];
    const float* w_ff1 = (const float*)d_in[11];
    const float* w_ff2 = (const float*)d_in[12];
    const float* ln1_s = (const float*)d_in[13];
    const float* ln1_b = (const float*)d_in[14];
    const float* ln2_s = (const float*)d_in[15];
    const float* ln2_b = (const float*)d_in[16];
    const float* ln3_s = (const float*)d_in[17];
    const float* ln3_b = (const float*)d_in[18];
    float* out = (float*)d_out;

    float *x, *lnb, *q, *k, *v, *ao, *tmp, *ff, *sc;
    cudaGetSymbolAddress((void**)&x,   g_x);
    cudaGetSymbolAddress((void**)&lnb, g_ln);
    cudaGetSymbolAddress((void**)&q,   g_q);
    cudaGetSymbolAddress((void**)&k,   g_k);
    cudaGetSymbolAddress((void**)&v,   g_v);
    cudaGetSymbolAddress((void**)&ao,  g_ao);
    cudaGetSymbolAddress((void**)&tmp, g_tmp);
    cudaGetSymbolAddress((void**)&ff,  g_ff);
    cudaGetSymbolAddress((void**)&sc,  g_sc);

    const long long nX = (long long)Bv * CAPv * Dv;

    // index machinery + extraction
    scan_kernel<<<Bv, 512>>>(seq);
    zero_buf<<<(int)((nX + 255) / 256), 256>>>(x, nX);
    extract_kernel<<<Bv * Sv, 192>>>(hid);

    // ---- block 1: masked self-attention -------------------------------------
    ln_rows<<<Bv * CAPv, 256>>>(x, lnb, ln1_s, ln1_b);
    mma_gemm<0><<<dim3(12, 40, 1), 256>>>(lnb, wq_s, q, 5120, 768, 768, 768, 768, 768, 1, 0,0,0,0,0,0, 1.f);
    mma_gemm<0><<<dim3(12, 40, 1), 256>>>(lnb, wk_s, k, 5120, 768, 768, 768, 768, 768, 1, 0,0,0,0,0,0, 1.f);
    mma_gemm<0><<<dim3(12, 40, 1), 256>>>(lnb, wv_s, v, 5120, 768, 768, 768, 768, 768, 1, 0,0,0,0,0,0, 1.f);
    mma_gemm<1><<<dim3(10, 5, Bv * Hv), 256>>>(q, k, sc, CAPv, CAPv, DHv, Dv, Dv, CAPv,
        Hv, (long long)CAPv * Dv, DHv, (long long)CAPv * Dv, DHv,
        (long long)Hv * CAPv * CAPv, (long long)CAPv * CAPv, 0.125f);
    softmax_rows<<<Bv * Hv * CAPv, 256>>>(sc, CAPv, 1);
    mma_gemm<0><<<dim3(1, 5, Bv * Hv), 256>>>(sc, v, ao, CAPv, DHv, CAPv, CAPv, Dv, Dv,
        Hv, (long long)Hv * CAPv * CAPv, (long long)CAPv * CAPv,
        (long long)CAPv * Dv, DHv, (long long)CAPv * Dv, DHv, 1.f);
    mma_gemm<0><<<dim3(12, 40, 1), 256>>>(ao, wo_s, tmp, 5120, 768, 768, 768, 768, 768, 1, 0,0,0,0,0,0, 1.f);
    add_inplace<<<(int)((nX + 255) / 256), 256>>>(x, tmp, nX);

    // ---- block 2: cross-attention to img ------------------------------------
    ln_rows<<<Bv * CAPv, 256>>>(x, lnb, ln2_s, ln2_b);
    mma_gemm<0><<<dim3(12, 40, 1), 256>>>(lnb, wq_c, q, 5120, 768, 768, 768, 768, 768, 1, 0,0,0,0,0,0, 1.f);
    mma_gemm<0><<<dim3(12, 64, 1), 256>>>(img, wk_c, k, 8192, 768, 768, 768, 768, 768, 1, 0,0,0,0,0,0, 1.f);
    mma_gemm<0><<<dim3(12, 64, 1), 256>>>(img, wv_c, v, 8192, 768, 768, 768, 768, 768, 1, 0,0,0,0,0,0, 1.f);
    mma_gemm<1><<<dim3(16, 5, Bv * Hv), 256>>>(q, k, sc, CAPv, NIMG, DHv, Dv, Dv, NIMG,
        Hv, (long long)CAPv * Dv, DHv, (long long)NIMG * Dv, DHv,
        (long long)Hv * CAPv * NIMG, (long long)CAPv * NIMG, 0.125f);
    softmax_rows<<<Bv * Hv * CAPv, 256>>>(sc, NIMG, 0);
    mma_gemm<0><<<dim3(1, 5, Bv * Hv), 256>>>(sc, v, ao, CAPv, DHv, NIMG, NIMG, Dv, Dv,
        Hv, (long long)Hv * CAPv * NIMG, (long long)CAPv * NIMG,
        (long long)NIMG * Dv, DHv, (long long)CAPv * Dv, DHv, 1.f);
    mma_gemm<0><<<dim3(12, 40, 1), 256>>>(ao, wo_c, tmp, 5120, 768, 768, 768, 768, 768, 1, 0,0,0,0,0,0, 1.f);
    add_inplace<<<(int)((nX + 255) / 256), 256>>>(x, tmp, nX);

    // ---- FFN ------------------------------------------------------------------
    ln_rows<<<Bv * CAPv, 256>>>(x, lnb, ln3_s, ln3_b);
    mma_gemm<0><<<dim3(48, 40, 1), 256>>>(lnb, w_ff1, ff, 5120, FFv, 768, 768, FFv, FFv, 1, 0,0,0,0,0,0, 1.f);
    gelu_inplace<<<(int)(((long long)5120 * FFv + 255) / 256), 256>>>(ff, (long long)5120 * FFv);
    mma_gemm<0><<<dim3(12, 40, 1), 256>>>(ff, w_ff2, tmp, 5120, 768, FFv, FFv, 768, 768, 1, 0,0,0,0,0,0, 1.f);
    add_inplace<<<(int)((nX + 255) / 256), 256>>>(x, tmp, nX);

    // ---- outputs: [hid_new | x] ----------------------------------------------
    write_hid<<<(int)(((long long)Bv * Sv * Dv + 255) / 256), 256>>>(hid, out);
    write_x<<<(int)((nX + 255) / 256), 256>>>(out);
}

// round 17
// speedup vs baseline: 1.8866x; 1.2670x over previous
#include <cuda_runtime.h>
#include <math.h>
#include <stdint.h>

#define Bv 8
#define Sv 4096
#define Dv 768
#define NIMG 1024
#define FFv 3072
#define CAPv 640
#define Hv 12
#define DHv 64
#define SOCv 3
#define EOSv 2

// ---------------- scratch (device globals) -------------------------------------
__device__ __align__(16) float g_x  [Bv*CAPv*Dv];
__device__ __align__(16) float g_ln [Bv*CAPv*Dv];
__device__ __align__(16) float g_q  [Bv*CAPv*Dv];
__device__ __align__(16) float g_k  [Bv*NIMG*Dv];
__device__ __align__(16) float g_v  [Bv*NIMG*Dv];
__device__ __align__(16) float g_ao [Bv*CAPv*Dv];
__device__ __align__(16) float g_ff [Bv*CAPv*FFv];
__device__ __align__(16) float g_sc [(size_t)Bv*Hv*CAPv*NIMG];
__device__ int   g_pos[Bv*Sv];
__device__ int   g_soc[Bv*Sv];
__device__ int   g_cnt[Bv];

// ---------------- SOC/EOS prefix scan: 1 block per batch row ------------------
__global__ void scan_kernel(const int* __restrict__ seq) {
    __shared__ int sh[512];
    __shared__ int pref[513];
    int b = blockIdx.x, t = threadIdx.x;
    const int* row = seq + b * Sv;
    int tok[8];
#pragma unroll
    for (int i = 0; i < 8; i++) tok[i] = row[t * 8 + i];

    int e = 0;
#pragma unroll
    for (int i = 0; i < 8; i++) e += (tok[i] == EOSv);
    sh[t] = e;
    __syncthreads();
    if (t == 0) { int a = 0; for (int i = 0; i < 512; i++) { pref[i] = a; a += sh[i]; } pref[512] = a; }
    __syncthreads();
    int ebefore = pref[t];

    int ecur = ebefore, sc = 0;
#pragma unroll
    for (int i = 0; i < 8; i++) { if (tok[i] == SOCv && ecur == 0) sc++; ecur += (tok[i] == EOSv); }
    __syncthreads();
    sh[t] = sc;
    __syncthreads();
    if (t == 0) { int a = 0; for (int i = 0; i < 512; i++) { pref[i] = a; a += sh[i]; } pref[512] = a; }
    __syncthreads();

    int p = pref[t];
    ecur = ebefore;
#pragma unroll
    for (int i = 0; i < 8; i++) {
        int idx = b * Sv + t * 8 + i;
        bool v = (tok[i] == SOCv && ecur == 0);
        g_soc[idx] = v ? 1 : 0;
        g_pos[idx] = v ? p : CAPv;
        if (v) p++;
        ecur += (tok[i] == EOSv);
    }
    if (t == 0) g_cnt[b] = pref[512];
}

// ---------------- extract / zero -----------------------------------------------
__global__ void zero_buf4(float4* __restrict__ x, long long n4) {
    long long i = (long long)blockIdx.x * blockDim.x + threadIdx.x;
    if (i < n4) x[i] = make_float4(0.f, 0.f, 0.f, 0.f);
}

__global__ void extract_kernel(const float4* __restrict__ hid4) {
    int t = blockIdx.x;          // token index over B*S
    if (!g_soc[t]) return;
    int p = g_pos[t];
    if (p >= CAPv) return;
    int b = t / Sv;
    const float4* src = hid4 + (long long)t * (Dv / 4);
    float4* dst = ((float4*)g_x) + (long long)(b * CAPv + p) * (Dv / 4);
    dst[threadIdx.x] = src[threadIdx.x];
}

// ---------------- LayerNorm (1 block per row of 768) --------------------------
__global__ void ln_rows(const float* __restrict__ x, float* __restrict__ y,
                        const float* __restrict__ g, const float* __restrict__ be) {
    int row = blockIdx.x;
    const float* px = x + (long long)row * Dv;
    float* py = y + (long long)row * Dv;
    __shared__ float red[64];
    float s = 0.f, s2 = 0.f;
    for (int d = threadIdx.x; d < Dv; d += blockDim.x) { float v = px[d]; s += v; s2 += v * v; }
#pragma unroll
    for (int o = 16; o > 0; o >>= 1) { s += __shfl_down_sync(~0u, s, o); s2 += __shfl_down_sync(~0u, s2, o); }
    int lane = threadIdx.x & 31, w = threadIdx.x >> 5;
    if (lane == 0) { red[w] = s; red[w + 32] = s2; }
    __syncthreads();
    if (threadIdx.x == 0) {
        float a = 0.f, a2 = 0.f;
        for (int i = 0; i < (int)(blockDim.x >> 5); i++) { a += red[i]; a2 += red[i + 32]; }
        float mu = a / Dv;
        float var = a2 / Dv - mu * mu;
        red[0] = mu;
        red[1] = rsqrtf(var + 1e-5f);
    }
    __syncthreads();
    float mu = red[0], rs = red[1];
    for (int d = threadIdx.x; d < Dv; d += blockDim.x)
        py[d] = (px[d] - mu) * rs * g[d] + be[d];
}

// ---------------- TF32 tensor-core batched GEMM (R6-proven mainloop) -----------
// C = alpha*A@op(B) [+RES] [gelu]; TRANSB=0: B[K,N], 1: B[N,K]^T
__device__ __forceinline__ uint32_t f2tf32(float v) {
    uint32_t u;
    asm("cvt.rna.tf32.f32 %0, %1;" : "=r"(u) : "f"(v));
    return u;
}

__device__ __forceinline__ void mma_tf32(float* d, const uint32_t* a, const uint32_t* b) {
    asm volatile(
        "mma.sync.aligned.m16n8k8.row.col.f32.tf32.tf32.f32 "
        "{%0,%1,%2,%3},{%4,%5,%6,%7},{%8,%9},{%0,%1,%2,%3};"
        : "+f"(d[0]), "+f"(d[1]), "+f"(d[2]), "+f"(d[3])
        : "r"(a[0]), "r"(a[1]), "r"(a[2]), "r"(a[3]), "r"(b[0]), "r"(b[1]));
}

__device__ __forceinline__ float gelu1(float v) {
    float u = 0.7978845608028654f * (v + 0.044715f * v * v * v);
    return 0.5f * v * (1.f + tanhf(u));
}

template <int TRANSB, int ACT>
__global__ void __launch_bounds__(256)
mma_gemm(const float* __restrict__ A, const float* __restrict__ Bm,
         const float* __restrict__ RES, float* __restrict__ C,
         int M, int Nn, int K, int lda, int ldb, int ldc,
         int Hn, long long sAb, long long sAh, long long sBb, long long sBh,
         long long sCb, long long sCh, float alpha) {
    int z = blockIdx.z;
    int bb = z / Hn, hh = z % Hn;
    A += bb * sAb + hh * sAh;
    Bm += bb * sBb + hh * sBh;
    C += bb * sCb + hh * sCh;
    if (RES) RES += bb * sCb + hh * sCh;

    __shared__ float As[128][36];   // [m][k], pad -> conflict-free frag loads
    __shared__ float Bs[32][68];    // [k][n]

    int tid = threadIdx.x;
    int lane = tid & 31, warp = tid >> 5;
    int wm = warp >> 1, wn = warp & 1;        // 4 x 2 warp grid
    int g = lane >> 2, cq = lane & 3;
    int rb = blockIdx.y * 128, cb = blockIdx.x * 64;

    float acc[2][4][4];
#pragma unroll
    for (int mi = 0; mi < 2; mi++)
#pragma unroll
        for (int ni = 0; ni < 4; ni++)
#pragma unroll
            for (int i = 0; i < 4; i++) acc[mi][ni][i] = 0.f;

    for (int k0 = 0; k0 < K; k0 += 32) {
        // stage A (128x32), coalesced along k
#pragma unroll
        for (int i = 0; i < 16; i++) {
            int idx = tid + i * 256;
            int r = idx >> 5, c = idx & 31;
            int gr = rb + r, gc = k0 + c;
            float v = (gr < M && gc < K) ? A[(long long)gr * lda + gc] : 0.f;
            As[r][c] = __uint_as_float(f2tf32(v));
        }
        // stage B (32x64)
#pragma unroll
        for (int i = 0; i < 8; i++) {
            int idx = tid + i * 256;
            if (TRANSB) {
                int n = idx >> 5, kk = idx & 31;           // coalesced along K
                int gn = cb + n, gk = k0 + kk;
                float v = (gn < Nn && gk < K) ? Bm[(long long)gn * ldb + gk] : 0.f;
                Bs[kk][n] = __uint_as_float(f2tf32(v));
            } else {
                int kk = idx >> 6, n = idx & 63;           // coalesced along N
                int gk = k0 + kk, gn = cb + n;
                float v = (gk < K && gn < Nn) ? Bm[(long long)gk * ldb + gn] : 0.f;
                Bs[kk][n] = __uint_as_float(f2tf32(v));
            }
        }
        __syncthreads();

#pragma unroll
        for (int ks = 0; ks < 4; ks++) {
            int kk = ks * 8;
            uint32_t a[2][4], b[4][2];
#pragma unroll
            for (int mi = 0; mi < 2; mi++) {
                int row = wm * 32 + mi * 16 + g;
                a[mi][0] = __float_as_uint(As[row][kk + cq]);
                a[mi][1] = __float_as_uint(As[row + 8][kk + cq]);
                a[mi][2] = __float_as_uint(As[row][kk + cq + 4]);
                a[mi][3] = __float_as_uint(As[row + 8][kk + cq + 4]);
            }
#pragma unroll
            for (int ni = 0; ni < 4; ni++) {
                int col = wn * 32 + ni * 8 + g;
                b[ni][0] = __float_as_uint(Bs[kk + cq][col]);
                b[ni][1] = __float_as_uint(Bs[kk + cq + 4][col]);
            }
#pragma unroll
            for (int mi = 0; mi < 2; mi++)
#pragma unroll
                for (int ni = 0; ni < 4; ni++)
                    mma_tf32(acc[mi][ni], a[mi], b[ni]);
        }
        __syncthreads();
    }

    // epilogue (R6-proven mapping + fused ACT/RES)
#pragma unroll
    for (int mi = 0; mi < 2; mi++) {
        int row0 = rb + wm * 32 + mi * 16 + g;
#pragma unroll
        for (int ni = 0; ni < 4; ni++) {
            int col0 = cb + wn * 32 + ni * 8 + 2 * cq;
#pragma unroll
            for (int i = 0; i < 4; i++) {
                int rr = row0 + (i >> 1) * 8;
                int cc = col0 + (i & 1);
                if (rr < M && cc < Nn) {
                    long long idx = (long long)rr * ldc + cc;
                    float v = alpha * acc[mi][ni][i];
                    if (ACT) v = gelu1(v);
                    if (RES) v += RES[idx];
                    C[idx] = v;
                }
            }
        }
    }
}

// ---------------- single-pass masked softmax (register-cached) -----------------
__global__ void softmax_rows(float* __restrict__ sc, int Lk, int useMask) {
    long long row = blockIdx.x;                 // over B*H*CAP
    int b = (int)(row / (Hv * CAPv));
    float* p = sc + row * (long long)Lk;
    int c = useMask ? g_cnt[b] : Lk;
    __shared__ float red[32];
    int tid = threadIdx.x;
    int lane = tid & 31, w = tid >> 5;
    int nw = blockDim.x >> 5;
    int cnt = (Lk + 255) / 256;                 // <= 4

    float r[4];
    float m = -3e38f;
#pragma unroll 4
    for (int j = 0; j < 4; j++) {
        if (j >= cnt) break;
        int i = tid + j * 256;
        float v = -3e38f;
        if (i < Lk) v = (i < c) ? p[i] : -1e9f;
        r[j] = v;
        m = fmaxf(m, v);
    }
#pragma unroll
    for (int o = 16; o > 0; o >>= 1) m = fmaxf(m, __shfl_down_sync(~0u, m, o));
    if (lane == 0) red[w] = m;
    __syncthreads();
    if (tid == 0) { float a = -3e38f; for (int i = 0; i < nw; i++) a = fmaxf(a, red[i]); red[0] = a; }
    __syncthreads();
    m = red[0];
    __syncthreads();

    float s = 0.f;
#pragma unroll 4
    for (int j = 0; j < 4; j++) {
        if (j >= cnt) break;
        int i = tid + j * 256;
        if (i < Lk) { float e = expf(r[j] - m); r[j] = e; s += e; }
    }
#pragma unroll
    for (int o = 16; o > 0; o >>= 1) s += __shfl_down_sync(~0u, s, o);
    if (lane == 0) red[w] = s;
    __syncthreads();
    if (tid == 0) { float a = 0.f; for (int i = 0; i < nw; i++) a += red[i]; red[0] = a; }
    __syncthreads();
    float inv = 1.f / red[0];
#pragma unroll 4
    for (int j = 0; j < 4; j++) {
        if (j >= cnt) break;
        int i = tid + j * 256;
        if (i < Lk) p[i] = r[j] * inv;
    }
}

// ---------------- outputs -------------------------------------------------------
__global__ void write_hid(const float4* __restrict__ hid4, float4* __restrict__ out4) {
    int t = blockIdx.x;                 // token over B*S; 192 threads x float4
    long long base = (long long)t * (Dv / 4);
    if (g_soc[t]) {
        int p = g_pos[t];
        if (p > CAPv - 1) p = CAPv - 1;
        int b = t / Sv;
        const float4* src = ((const float4*)g_x) + (long long)(b * CAPv + p) * (Dv / 4);
        out4[base + threadIdx.x] = src[threadIdx.x];
    } else {
        out4[base + threadIdx.x] = hid4[base + threadIdx.x];
    }
}

__global__ void write_x(float4* __restrict__ out4) {
    long long i = (long long)blockIdx.x * blockDim.x + threadIdx.x;
    const long long n4 = (long long)Bv * CAPv * Dv / 4;
    if (i < n4) out4[(long long)Bv * Sv * Dv / 4 + i] = ((const float4*)g_x)[i];
}

// ---------------- launch --------------------------------------------------------
extern "C" void kernel_launch(void* const* d_in, const int* in_sizes, int n_in,
                              void* d_out, int out_size) {
    const float* img   = (const float*)d_in[0];
    const float* hid   = (const float*)d_in[1];
    const int*   seq   = (const int*)  d_in[2];
    const float* wq_s  = (const float*)d_in[3];
    const float* wk_s  = (const float*)d_in[4];
    const float* wv_s  = (const float*)d_in[5];
    const float* wo_s  = (const float*)d_in[6];
    const float* wq_c  = (const float*)d_in[7];
    const float* wk_c  = (const float*)d_in[8];
    const float* wv_c  = (const float*)d_in[9];
    const float* wo_c  = (const float*)d_in[10];
    const float* w_ff1 = (const float*)d_in[11];
    const float* w_ff2 = (const float*)d_in[12];
    const float* ln1_s = (const float*)d_in[13];
    const float* ln1_b = (const float*)d_in[14];
    const float* ln2_s = (const float*)d_in[15];
    const float* ln2_b = (const float*)d_in[16];
    const float* ln3_s = (const float*)d_in[17];
    const float* ln3_b = (const float*)d_in[18];
    float* out = (float*)d_out;

    float *x, *lnb, *q, *k, *v, *ao, *ff, *sc;
    cudaGetSymbolAddress((void**)&x,   g_x);
    cudaGetSymbolAddress((void**)&lnb, g_ln);
    cudaGetSymbolAddress((void**)&q,   g_q);
    cudaGetSymbolAddress((void**)&k,   g_k);
    cudaGetSymbolAddress((void**)&v,   g_v);
    cudaGetSymbolAddress((void**)&ao,  g_ao);
    cudaGetSymbolAddress((void**)&ff,  g_ff);
    cudaGetSymbolAddress((void**)&sc,  g_sc);

    const long long nX = (long long)Bv * CAPv * Dv;

    // index machinery + extraction
    scan_kernel<<<Bv, 512>>>(seq);
    zero_buf4<<<(int)((nX / 4 + 255) / 256), 256>>>((float4*)x, nX / 4);
    extract_kernel<<<Bv * Sv, Dv / 4>>>((const float4*)hid);

    // ---- block 1: masked self-attention -------------------------------------
    ln_rows<<<Bv * CAPv, 256>>>(x, lnb, ln1_s, ln1_b);
    mma_gemm<0,0><<<dim3(12, 40, 1), 256>>>(lnb, wq_s, nullptr, q, 5120, 768, 768, 768, 768, 768, 1, 0,0,0,0,0,0, 1.f);
    mma_gemm<0,0><<<dim3(12, 40, 1), 256>>>(lnb, wk_s, nullptr, k, 5120, 768, 768, 768, 768, 768, 1, 0,0,0,0,0,0, 1.f);
    mma_gemm<0,0><<<dim3(12, 40, 1), 256>>>(lnb, wv_s, nullptr, v, 5120, 768, 768, 768, 768, 768, 1, 0,0,0,0,0,0, 1.f);
    mma_gemm<1,0><<<dim3(10, 5, Bv * Hv), 256>>>(q, k, nullptr, sc, CAPv, CAPv, DHv, Dv, Dv, CAPv,
        Hv, (long long)CAPv * Dv, DHv, (long long)CAPv * Dv, DHv,
        (long long)Hv * CAPv * CAPv, (long long)CAPv * CAPv, 0.125f);
    softmax_rows<<<Bv * Hv * CAPv, 256>>>(sc, CAPv, 1);
    mma_gemm<0,0><<<dim3(1, 5, Bv * Hv), 256>>>(sc, v, nullptr, ao, CAPv, DHv, CAPv, CAPv, Dv, Dv,
        Hv, (long long)Hv * CAPv * CAPv, (long long)CAPv * CAPv,
        (long long)CAPv * Dv, DHv, (long long)CAPv * Dv, DHv, 1.f);
    mma_gemm<0,0><<<dim3(12, 40, 1), 256>>>(ao, wo_s, x, x, 5120, 768, 768, 768, 768, 768, 1, 0,0,0,0,0,0, 1.f);

    // ---- block 2: cross-attention to img ------------------------------------
    ln_rows<<<Bv * CAPv, 256>>>(x, lnb, ln2_s, ln2_b);
    mma_gemm<0,0><<<dim3(12, 40, 1), 256>>>(lnb, wq_c, nullptr, q, 5120, 768, 768, 768, 768, 768, 1, 0,0,0,0,0,0, 1.f);
    mma_gemm<0,0><<<dim3(12, 64, 1), 256>>>(img, wk_c, nullptr, k, 8192, 768, 768, 768, 768, 768, 1, 0,0,0,0,0,0, 1.f);
    mma_gemm<0,0><<<dim3(12, 64, 1), 256>>>(img, wv_c, nullptr, v, 8192, 768, 768, 768, 768, 768, 1, 0,0,0,0,0,0, 1.f);
    mma_gemm<1,0><<<dim3(16, 5, Bv * Hv), 256>>>(q, k, nullptr, sc, CAPv, NIMG, DHv, Dv, Dv, NIMG,
        Hv, (long long)CAPv * Dv, DHv, (long long)NIMG * Dv, DHv,
        (long long)Hv * CAPv * NIMG, (long long)CAPv * NIMG, 0.125f);
    softmax_rows<<<Bv * Hv * CAPv, 256>>>(sc, NIMG, 0);
    mma_gemm<0,0><<<dim3(1, 5, Bv * Hv), 256>>>(sc, v, nullptr, ao, CAPv, DHv, NIMG, NIMG, Dv, Dv,
        Hv, (long long)Hv * CAPv * NIMG, (long long)CAPv * NIMG,
        (long long)NIMG * Dv, DHv, (long long)CAPv * Dv, DHv, 1.f);
    mma_gemm<0,0><<<dim3(12, 40, 1), 256>>>(ao, wo_c, x, x, 5120, 768, 768, 768, 768, 768, 1, 0,0,0,0,0,0, 1.f);

    // ---- FFN (GELU fused into ff1 epilogue, residual into ff2) ----------------
    ln_rows<<<Bv * CAPv, 256>>>(x, lnb, ln3_s, ln3_b);
    mma_gemm<0,1><<<dim3(48, 40, 1), 256>>>(lnb, w_ff1, nullptr, ff, 5120, FFv, 768, 768, FFv, FFv, 1, 0,0,0,0,0,0, 1.f);
    mma_gemm<0,0><<<dim3(12, 40, 1), 256>>>(ff, w_ff2, x, x, 5120, 768, FFv, FFv, 768, 768, 1, 0,0,0,0,0,0, 1.f);

    // ---- outputs: [hid_new | x] ----------------------------------------------
    write_hid<<<Bv * Sv, Dv / 4>>>((const float4*)hid, (float4*)out);
    write_x<<<(int)((nX / 4 + 255) / 256), 256>>>((float4*)out);
}